// round 1
// baseline (speedup 1.0000x reference)
#include <cuda_runtime.h>
#include <cuda_bf16.h>
#include <cstdint>

// Problem constants
#define NN      202500          // 150*150*9 anchors
#define K_PRE   6000            // pre-NMS top-k
#define K_POST  300             // post-NMS output rows
#define NW      94              // ceil(6000/64) bitmask words
#define CAP     16384           // candidate buffer capacity
#define IOU_TH  0.7f
#define MIN_SZ  0.016f          // 16/1000

typedef unsigned long long u64;
typedef unsigned int u32;

// ---------------- device scratch (no allocations allowed) ----------------
__device__ u64    g_keys[NN];           // sort keys (fkey<<32 | ~idx)
__device__ float4 g_boxes[NN];          // decoded+clipped boxes
__device__ u32    g_hist[65536];        // histogram on top-16 key bits
__device__ u32    g_thresh;             // bucket threshold
__device__ int    g_M;                  // candidate count
__device__ u64    g_cand[CAP];          // candidate keys
__device__ float4 g_sbox[K_PRE];        // score-sorted top-6000 boxes
__device__ u64    g_valid[NW];          // validity bitmask over sorted slots
__device__ u64    g_supp[(size_t)K_PRE * NW]; // suppression matrix rows (upper-tri words)

// ---------------- kernel 0: zero state ----------------
__global__ void k_zero() {
    int t = blockIdx.x * blockDim.x + threadIdx.x;
    int stride = gridDim.x * blockDim.x;
    for (int b = t; b < 65536; b += stride) g_hist[b] = 0u;
    if (t < NW) g_valid[t] = 0ull;
    if (t == 0) g_M = 0;
}

// ---------------- kernel 1: score + decode + key + histogram ----------------
__global__ void k_prep(const float* __restrict__ cls,
                       const float* __restrict__ loc,
                       const float* __restrict__ anc) {
    int n = blockIdx.x * blockDim.x + threadIdx.x;
    if (n >= NN) return;

    // softmax score, computed exactly like jax.nn.softmax (max-sub, exp, div)
    float c0 = cls[2 * n + 0];
    float c1 = cls[2 * n + 1];
    float m  = fmaxf(c0, c1);
    float e0 = expf(c0 - m);
    float e1 = expf(c1 - m);
    float s  = __fdiv_rn(e1, e0 + e1);

    // anchor -> cxcywh priors
    float ax0 = anc[4 * n + 0], ay0 = anc[4 * n + 1];
    float ax1 = anc[4 * n + 2], ay1 = anc[4 * n + 3];
    float pcx = (ax1 + ax0) * 0.5f;
    float pcy = (ay1 + ay0) * 0.5f;
    float pw  = ax1 - ax0;
    float ph  = ay1 - ay0;

    // decode
    float tx = loc[4 * n + 0], ty = loc[4 * n + 1];
    float tw = loc[4 * n + 2], th = loc[4 * n + 3];
    float cx = tx * pw + pcx;
    float cy = ty * ph + pcy;
    float w  = expf(tw) * pw;
    float h  = expf(th) * ph;

    // cxcywh -> xyxy, clip [0,1]
    float X0 = cx - w * 0.5f;
    float Y0 = cy - h * 0.5f;
    float X1 = cx + w * 0.5f;
    float Y1 = cy + h * 0.5f;
    X0 = fminf(fmaxf(X0, 0.0f), 1.0f);
    Y0 = fminf(fmaxf(Y0, 0.0f), 1.0f);
    X1 = fminf(fmaxf(X1, 0.0f), 1.0f);
    Y1 = fminf(fmaxf(Y1, 0.0f), 1.0f);

    float ws = X1 - X0;
    float hs = Y1 - Y0;
    bool valid = (ws >= MIN_SZ) && (hs >= MIN_SZ);
    float sm = valid ? s : -1.0f;

    // orderable float key
    u32 b  = __float_as_uint(sm);
    u32 fk = b ^ ((b >> 31) ? 0xFFFFFFFFu : 0x80000000u);

    g_keys[n]  = ((u64)fk << 32) | (u32)(~(u32)n);
    g_boxes[n] = make_float4(X0, Y0, X1, Y1);
    atomicAdd(&g_hist[fk >> 16], 1u);
}

// ---------------- kernel 2: find bucket threshold ----------------
__global__ void k_thresh() {
    __shared__ u32 csum[1024];
    int t = threadIdx.x;
    u32 s = 0;
    #pragma unroll 4
    for (int b = 0; b < 64; b++) s += g_hist[t * 64 + b];
    csum[t] = s;
    __syncthreads();
    if (t == 0) {
        u32 acc = 0;
        int thr = 0;
        for (int c = 1023; c >= 0; c--) {
            if (acc + csum[c] >= (u32)K_PRE) {
                u32 a2 = acc;
                for (int b = 63; b >= 0; b--) {
                    a2 += g_hist[c * 64 + b];
                    if (a2 >= (u32)K_PRE) { thr = c * 64 + b; break; }
                }
                break;
            }
            acc += csum[c];
        }
        g_thresh = (u32)thr;
    }
}

// ---------------- kernel 3: compact candidates ----------------
__global__ void k_compact() {
    int n = blockIdx.x * blockDim.x + threadIdx.x;
    if (n >= NN) return;
    u64 k = g_keys[n];
    if ((u32)(k >> 48) >= g_thresh) {
        int p = atomicAdd(&g_M, 1);
        if (p < CAP) g_cand[p] = k;
    }
}

// ---------------- kernel 4: rank-sort top-6000 + gather boxes + valid bits ----------------
__global__ void k_rank() {
    int m = g_M; if (m > CAP) m = CAP;
    if (blockIdx.x * 256 >= m) return;
    int i = blockIdx.x * 256 + threadIdx.x;
    bool active = (i < m);
    u64 mykey = active ? g_cand[i] : 0ull;
    int rank = 0;
    __shared__ u64 tile[256];
    for (int base = 0; base < m; base += 256) {
        int j = base + threadIdx.x;
        tile[threadIdx.x] = (j < m) ? g_cand[j] : 0ull;
        __syncthreads();
        int lim = min(256, m - base);
        if (active) {
            #pragma unroll 8
            for (int tt = 0; tt < lim; tt++) rank += (tile[tt] > mykey);
        }
        __syncthreads();
    }
    if (active && rank < K_PRE) {
        u32 idx = ~(u32)mykey;
        g_sbox[rank] = g_boxes[idx];
        u32 fk = (u32)(mykey >> 32);
        if (fk >= 0x80000000u)  // masked score >= 0 -> valid
            atomicOr(&g_valid[rank >> 6], 1ull << (rank & 63));
    }
}

// ---------------- kernel 5: suppression matrix ----------------
__global__ void k_iou() {
    int bx = blockIdx.x;  // column word 0..93
    int by = blockIdx.y;  // row tile   0..93
    if (bx < by) return;  // only upper triangle (incl. diagonal) is ever read

    __shared__ float4 cb[64];
    __shared__ float  ca[64];
    int t  = threadIdx.x;       // 0..63
    int j0 = bx * 64;
    int jj = j0 + t;
    float4 zb = make_float4(0.f, 0.f, 0.f, 0.f);
    float4 c  = (jj < K_PRE) ? g_sbox[jj] : zb;
    cb[t] = c;
    ca[t] = (c.z - c.x) * (c.w - c.y);
    __syncthreads();

    int i = by * 64 + t;
    if (i >= K_PRE) return;
    float4 a = g_sbox[i];
    float aarea = (a.z - a.x) * (a.w - a.y);

    u64 bits = 0ull;
    #pragma unroll 4
    for (int jt = 0; jt < 64; jt++) {
        int j = j0 + jt;
        float4 b = cb[jt];
        float ltx = fmaxf(a.x, b.x);
        float lty = fmaxf(a.y, b.y);
        float rbx = fminf(a.z, b.z);
        float rby = fminf(a.w, b.w);
        float wx = fmaxf(rbx - ltx, 0.0f);
        float wy = fmaxf(rby - lty, 0.0f);
        float inter = wx * wy;
        float denom = ((aarea + ca[jt]) - inter) + 1e-12f;
        float iou = __fdiv_rn(inter, denom);
        bool supp = (j > i) && (j < K_PRE) && (iou > IOU_TH);
        bits |= ((u64)supp) << jt;
    }
    g_supp[(size_t)i * NW + bx] = bits;
}

// ---------------- kernel 6: serial greedy NMS scan (1 warp), early exit at 300 keeps ----------------
__global__ void k_scan(float* __restrict__ out) {
    __shared__ u64 rem[NW];
    __shared__ u64 diag[64];
    __shared__ int sel[K_POST];
    __shared__ int s_cnt;
    __shared__ int s_done;

    int lane = threadIdx.x;
    for (int w = lane; w < NW; w += 32) rem[w] = 0ull;
    if (lane == 0) { s_cnt = 0; s_done = 0; }
    __syncwarp();

    for (int w = 0; w < NW; w++) {
        if (s_done) break;
        // prefetch this word's diagonal column (row i's word w for i in this word)
        for (int b = lane; b < 64; b += 32) {
            int i = w * 64 + b;
            diag[b] = (i < K_PRE) ? g_supp[(size_t)i * NW + w] : 0ull;
        }
        __syncwarp();

        u64 cur = 0ull;
        if (lane == 0) cur = g_valid[w] & ~rem[w];

        while (true) {
            int i = -1;
            if (lane == 0 && cur) {
                int b = __ffsll((long long)cur) - 1;
                i = w * 64 + b;
            }
            i = __shfl_sync(0xFFFFFFFFu, i, 0);
            if (i < 0) break;

            const u64* row = &g_supp[(size_t)i * NW];
            for (int w2 = w + lane; w2 < NW; w2 += 32) rem[w2] |= row[w2];

            if (lane == 0) {
                int cnum = s_cnt;
                sel[cnum] = i;
                s_cnt = cnum + 1;
                cur &= ~(1ull << (i & 63));
                cur &= ~diag[i & 63];
                if (cnum + 1 >= K_POST) { s_done = 1; cur = 0ull; }
            }
        }
        __syncwarp();
    }
    __syncwarp();

    int n = s_cnt;
    float4* out4 = reinterpret_cast<float4*>(out);
    for (int k = lane; k < K_POST; k += 32) {
        float4 b = make_float4(0.f, 0.f, 0.f, 0.f);
        if (k < n) b = g_sbox[sel[k]];
        out4[k] = b;
    }
}

// ---------------- launch ----------------
extern "C" void kernel_launch(void* const* d_in, const int* in_sizes, int n_in,
                              void* d_out, int out_size) {
    const float* cls = (const float*)d_in[0];   // (1, N, 2)
    const float* loc = (const float*)d_in[1];   // (1, N, 4)
    const float* anc = (const float*)d_in[2];   // (N, 4)
    float* out = (float*)d_out;                 // (300, 4)

    k_zero<<<64, 256>>>();
    k_prep<<<(NN + 255) / 256, 256>>>(cls, loc, anc);
    k_thresh<<<1, 1024>>>();
    k_compact<<<(NN + 255) / 256, 256>>>();
    k_rank<<<CAP / 256, 256>>>();
    k_iou<<<dim3(NW, NW), 64>>>();
    k_scan<<<1, 32>>>(out);
}

// round 2
// speedup vs baseline: 1.5750x; 1.5750x over previous
#include <cuda_runtime.h>
#include <cuda_bf16.h>
#include <cstdint>

// Problem constants
#define NN      202500          // 150*150*9 anchors
#define K_PRE   6000            // pre-NMS top-k
#define K_POST  300             // post-NMS output rows
#define NW      94              // ceil(6000/64) bitmask words (full matrix)
#define T_SMALL 1024            // restricted scan window
#define TW      16              // T_SMALL/64
#define CAP     16384           // candidate buffer capacity
#define IOU_TH  0.7f
#define MIN_SZ  0.016f          // 16/1000

typedef unsigned long long u64;
typedef unsigned int u32;

// ---------------- device scratch ----------------
__device__ u64    g_keys[NN];           // sort keys (fkey<<32 | ~idx)
__device__ float4 g_boxes[NN];          // decoded+clipped boxes
__device__ u32    g_hist[65536];        // histogram on top-16 key bits
__device__ u32    g_bcnt[65536];        // per-bucket scatter counters
__device__ u32    g_suf[65537];         // suffix sums: #keys with bucket >= b
__device__ u32    g_thresh;             // bucket threshold
__device__ u64    g_cand[CAP];          // candidate keys, grouped by bucket
__device__ float4 g_sbox[K_PRE];        // score-sorted top-6000 boxes
__device__ u64    g_valid[NW];          // validity bitmask over sorted slots
__device__ int    g_need;               // fallback-to-full-matrix flag
__device__ u64    g_supp[(size_t)K_PRE * NW]; // suppression matrix

// ---------------- kernel 0: zero state ----------------
__global__ void k_zero() {
    int t = blockIdx.x * blockDim.x + threadIdx.x;
    int stride = gridDim.x * blockDim.x;
    for (int b = t; b < 65536; b += stride) { g_hist[b] = 0u; g_bcnt[b] = 0u; }
    if (t < NW) g_valid[t] = 0ull;
    if (t == 0) g_need = 0;
}

// ---------------- kernel 1: score + decode + key + histogram ----------------
__global__ void k_prep(const float2* __restrict__ cls,
                       const float4* __restrict__ loc,
                       const float4* __restrict__ anc) {
    int n = blockIdx.x * blockDim.x + threadIdx.x;
    if (n >= NN) return;

    // softmax score, computed exactly like jax.nn.softmax (max-sub, exp, div)
    float2 c = cls[n];
    float m  = fmaxf(c.x, c.y);
    float e0 = expf(c.x - m);
    float e1 = expf(c.y - m);
    float s  = __fdiv_rn(e1, e0 + e1);

    // anchor -> cxcywh priors
    float4 A = anc[n];
    float pcx = (A.z + A.x) * 0.5f;
    float pcy = (A.w + A.y) * 0.5f;
    float pw  = A.z - A.x;
    float ph  = A.w - A.y;

    // decode
    float4 L = loc[n];
    float cx = L.x * pw + pcx;
    float cy = L.y * ph + pcy;
    float w  = expf(L.z) * pw;
    float h  = expf(L.w) * ph;

    // cxcywh -> xyxy, clip [0,1]
    float X0 = fminf(fmaxf(cx - w * 0.5f, 0.0f), 1.0f);
    float Y0 = fminf(fmaxf(cy - h * 0.5f, 0.0f), 1.0f);
    float X1 = fminf(fmaxf(cx + w * 0.5f, 0.0f), 1.0f);
    float Y1 = fminf(fmaxf(cy + h * 0.5f, 0.0f), 1.0f);

    bool valid = ((X1 - X0) >= MIN_SZ) && ((Y1 - Y0) >= MIN_SZ);
    float sm = valid ? s : -1.0f;

    // orderable float key
    u32 b  = __float_as_uint(sm);
    u32 fk = b ^ ((b >> 31) ? 0xFFFFFFFFu : 0x80000000u);

    g_keys[n]  = ((u64)fk << 32) | (u32)(~(u32)n);
    g_boxes[n] = make_float4(X0, Y0, X1, Y1);
    atomicAdd(&g_hist[fk >> 16], 1u);
}

// ---------------- kernel 2: bucket suffix sums + threshold ----------------
__global__ void k_suf() {
    __shared__ u32 csum[1024];
    __shared__ u32 coff[1024];
    int t = threadIdx.x;
    u32 s = 0;
    #pragma unroll 8
    for (int b = 0; b < 64; b++) s += g_hist[t * 64 + b];
    csum[t] = s;
    __syncthreads();
    if (t == 0) {
        u32 acc = 0;
        for (int c = 1023; c >= 0; c--) { coff[c] = acc; acc += csum[c]; }
    }
    __syncthreads();
    u32 acc = coff[t];
    for (int b = 63; b >= 0; b--) {
        int idx = t * 64 + b;
        u32 prev = acc;
        acc += g_hist[idx];
        g_suf[idx] = acc;
        if (prev < (u32)K_PRE && acc >= (u32)K_PRE) g_thresh = (u32)idx;
    }
    if (t == 1023) g_suf[65536] = 0u;
}

// ---------------- kernel 3: compact candidates into per-bucket regions ----------------
__global__ void k_compact() {
    int n = blockIdx.x * blockDim.x + threadIdx.x;
    if (n >= NN) return;
    u64 k = g_keys[n];
    u32 b = (u32)(k >> 48);
    if (b >= g_thresh) {
        u32 pos = g_suf[b + 1] + atomicAdd(&g_bcnt[b], 1u);
        if (pos < CAP) g_cand[pos] = k;
    }
}

// ---------------- kernel 4: within-bucket rank + gather boxes + valid bits ----------------
__global__ void k_rank() {
    u32 thr = g_thresh;
    u32 M = g_suf[thr]; if (M > CAP) M = CAP;
    u32 i = blockIdx.x * blockDim.x + threadIdx.x;
    if (i >= M) return;
    u64 key = g_cand[i];
    u32 b = (u32)(key >> 48);
    u32 start = g_suf[b + 1];
    u32 end   = g_suf[b]; if (end > M) end = M;
    u32 rank = start;
    for (u32 j = start; j < end; j++) rank += (g_cand[j] > key);
    if (rank < K_PRE) {
        u32 idx = ~(u32)key;
        g_sbox[rank] = g_boxes[idx];
        if ((u32)(key >> 32) >= 0x80000000u)  // masked score >= 0 -> valid
            atomicOr(&g_valid[rank >> 6], 1ull << (rank & 63));
    }
}

// ---------------- IOU word helper (div-free w/ exact fixup) ----------------
__device__ __forceinline__ u64 iou_word(float4 a, float aarea,
                                        const float4* cb, const float* ca) {
    u64 bits = 0ull, near_ = 0ull;
    #pragma unroll 8
    for (int jt = 0; jt < 64; jt++) {
        float4 b = cb[jt];
        float ltx = fmaxf(a.x, b.x);
        float lty = fmaxf(a.y, b.y);
        float rbx = fminf(a.z, b.z);
        float rby = fminf(a.w, b.w);
        float wx = fmaxf(rbx - ltx, 0.0f);
        float wy = fmaxf(rby - lty, 0.0f);
        float inter = wx * wy;
        float denom = ((aarea + ca[jt]) - inter) + 1e-12f;
        float m = IOU_TH * denom;
        bits  |= ((u64)(inter > m)) << jt;
        near_ |= ((u64)(fabsf(inter - m) <= 2e-6f * denom)) << jt;
    }
    if (near_) {  // rare: recompute exactly with the reference's division
        u64 nb = near_;
        while (nb) {
            int jt = __ffsll((long long)nb) - 1;
            nb &= nb - 1;
            float4 b = cb[jt];
            float wx = fmaxf(fminf(a.z, b.z) - fmaxf(a.x, b.x), 0.0f);
            float wy = fmaxf(fminf(a.w, b.w) - fmaxf(a.y, b.y), 0.0f);
            float inter = wx * wy;
            float denom = ((aarea + ca[jt]) - inter) + 1e-12f;
            bool supp = __fdiv_rn(inter, denom) > IOU_TH;
            bits = (bits & ~(1ull << jt)) | (((u64)supp) << jt);
        }
    }
    return bits;
}

// ---------------- kernel 5a: restricted T_SMALL x T_SMALL suppression ----------------
__global__ void k_iou_small() {
    int bx = blockIdx.x, by = blockIdx.y;
    if (bx < by) return;
    __shared__ float4 cb[64];
    __shared__ float  ca[64];
    int t = threadIdx.x;
    float4 c = g_sbox[bx * 64 + t];
    cb[t] = c;
    ca[t] = (c.z - c.x) * (c.w - c.y);
    __syncthreads();

    int i = by * 64 + t;
    float4 a = g_sbox[i];
    float aarea = (a.z - a.x) * (a.w - a.y);
    u64 bits = iou_word(a, aarea, cb, ca);
    if (bx == by) bits &= (t == 63) ? 0ull : (~0ull << (t + 1));  // j > i
    g_supp[(size_t)i * TW + bx] = bits;
}

// ---------------- kernel 6a: restricted scan; sets g_need if inconclusive ----------------
__global__ void k_scan_small(float* __restrict__ out) {
    __shared__ u64 rem[TW];
    __shared__ u64 diag[64];
    __shared__ int sel[K_POST];
    __shared__ int s_cnt;
    __shared__ int s_done;

    int lane = threadIdx.x;
    if (lane < TW) rem[lane] = 0ull;
    if (lane == 0) { s_cnt = 0; s_done = 0; }
    __syncwarp();

    for (int w = 0; w < TW; w++) {
        if (s_done) break;
        for (int b = lane; b < 64; b += 32)
            diag[b] = g_supp[(size_t)(w * 64 + b) * TW + w];
        __syncwarp();

        u64 cur = 0ull;
        if (lane == 0) cur = g_valid[w] & ~rem[w];

        while (true) {
            int i = -1;
            if (lane == 0 && cur) i = w * 64 + (__ffsll((long long)cur) - 1);
            i = __shfl_sync(0xFFFFFFFFu, i, 0);
            if (i < 0) break;

            const u64* row = &g_supp[(size_t)i * TW];
            for (int w2 = w + lane; w2 < TW; w2 += 32) rem[w2] |= row[w2];

            if (lane == 0) {
                int c = s_cnt;
                sel[c] = i;
                s_cnt = c + 1;
                cur &= ~(1ull << (i & 63));
                cur &= ~diag[i & 63];
                if (c + 1 >= K_POST) { s_done = 1; cur = 0ull; }
            }
        }
        __syncwarp();
    }
    __syncwarp();

    if (s_cnt < K_POST) {            // inconclusive within window -> full fallback
        if (lane == 0) g_need = 1;
        return;
    }
    float4* out4 = reinterpret_cast<float4*>(out);
    for (int k = lane; k < K_POST; k += 32) out4[k] = g_sbox[sel[k]];
}

// ---------------- kernel 5b: full matrix (guarded fallback) ----------------
__global__ void k_iou_full() {
    if (g_need == 0) return;
    int bx = blockIdx.x, by = blockIdx.y;
    if (bx < by) return;
    __shared__ float4 cb[64];
    __shared__ float  ca[64];
    int t = threadIdx.x;
    int jj = bx * 64 + t;
    float4 c = (jj < K_PRE) ? g_sbox[jj] : make_float4(0.f, 0.f, 0.f, 0.f);
    cb[t] = c;
    ca[t] = (c.z - c.x) * (c.w - c.y);
    __syncthreads();

    int i = by * 64 + t;
    if (i >= K_PRE) return;
    float4 a = g_sbox[i];
    float aarea = (a.z - a.x) * (a.w - a.y);
    u64 bits = iou_word(a, aarea, cb, ca);
    if (bx == by) bits &= (t == 63) ? 0ull : (~0ull << (t + 1));  // j > i
    // mask out-of-range columns in last word
    if (bx == NW - 1) bits &= (1ull << (K_PRE - 64 * (NW - 1))) - 1ull;
    g_supp[(size_t)i * NW + bx] = bits;
}

// ---------------- kernel 6b: full scan (guarded fallback) ----------------
__global__ void k_scan_full(float* __restrict__ out) {
    if (g_need == 0) return;
    __shared__ u64 rem[NW];
    __shared__ u64 diag[64];
    __shared__ int sel[K_POST];
    __shared__ int s_cnt;
    __shared__ int s_done;

    int lane = threadIdx.x;
    for (int w = lane; w < NW; w += 32) rem[w] = 0ull;
    if (lane == 0) { s_cnt = 0; s_done = 0; }
    __syncwarp();

    for (int w = 0; w < NW; w++) {
        if (s_done) break;
        for (int b = lane; b < 64; b += 32) {
            int i = w * 64 + b;
            diag[b] = (i < K_PRE) ? g_supp[(size_t)i * NW + w] : 0ull;
        }
        __syncwarp();

        u64 cur = 0ull;
        if (lane == 0) cur = g_valid[w] & ~rem[w];

        while (true) {
            int i = -1;
            if (lane == 0 && cur) i = w * 64 + (__ffsll((long long)cur) - 1);
            i = __shfl_sync(0xFFFFFFFFu, i, 0);
            if (i < 0) break;

            const u64* row = &g_supp[(size_t)i * NW];
            for (int w2 = w + lane; w2 < NW; w2 += 32) rem[w2] |= row[w2];

            if (lane == 0) {
                int c = s_cnt;
                sel[c] = i;
                s_cnt = c + 1;
                cur &= ~(1ull << (i & 63));
                cur &= ~diag[i & 63];
                if (c + 1 >= K_POST) { s_done = 1; cur = 0ull; }
            }
        }
        __syncwarp();
    }
    __syncwarp();

    int n = s_cnt;
    float4* out4 = reinterpret_cast<float4*>(out);
    for (int k = lane; k < K_POST; k += 32) {
        float4 b = make_float4(0.f, 0.f, 0.f, 0.f);
        if (k < n) b = g_sbox[sel[k]];
        out4[k] = b;
    }
}

// ---------------- launch ----------------
extern "C" void kernel_launch(void* const* d_in, const int* in_sizes, int n_in,
                              void* d_out, int out_size) {
    const float2* cls = (const float2*)d_in[0];   // (1, N, 2)
    const float4* loc = (const float4*)d_in[1];   // (1, N, 4)
    const float4* anc = (const float4*)d_in[2];   // (N, 4)
    float* out = (float*)d_out;                   // (300, 4)

    k_zero<<<64, 256>>>();
    k_prep<<<(NN + 255) / 256, 256>>>(cls, loc, anc);
    k_suf<<<1, 1024>>>();
    k_compact<<<(NN + 255) / 256, 256>>>();
    k_rank<<<CAP / 256, 256>>>();
    k_iou_small<<<dim3(TW, TW), 64>>>();
    k_scan_small<<<1, 32>>>(out);
    k_iou_full<<<dim3(NW, NW), 64>>>();   // no-op unless g_need
    k_scan_full<<<1, 32>>>(out);          // no-op unless g_need
}

// round 3
// speedup vs baseline: 1.5870x; 1.0076x over previous
#include <cuda_runtime.h>
#include <cuda_bf16.h>
#include <cstdint>

// Problem constants
#define NN      202500          // 150*150*9 anchors
#define K_PRE   6000            // pre-NMS top-k
#define K_POST  300             // post-NMS output rows
#define NWRD    94              // ceil(6000/64) suppression words per row
#define CAP     16384           // candidate buffer capacity
#define NB      148             // grid blocks (<= SM count, co-resident)
#define TPB     512             // threads per block
#define TOT     (NB*TPB)        // 75776
#define IOU_TH  0.7f
#define MIN_SZ  0.016f
#define CROWS   1024            // scan cache rows
#define CWRD    16              // scan cache words per row
#define NSTRIPR 12              // ceil(6000/512) row strips

typedef unsigned long long u64;
typedef unsigned int u32;

// ---------------- device scratch ----------------
__device__ u64    g_keys[NN];
__device__ float4 g_boxes[NN];
__device__ u32    g_hist[65536];        // zeroed by phase D of previous launch / static init
__device__ u32    g_bcnt[65536];        // ditto
__device__ u32    g_suf[65537];         // g_suf[65536] stays 0 forever
__device__ u32    g_thresh;
__device__ u64    g_cand[CAP];
__device__ float4 g_sbox[K_PRE];
__device__ u64    g_valid[NWRD];
__device__ u64    g_supp[(size_t)K_PRE * NWRD];
__device__ u32    g_barrier[8];

// ---------------- barrier reset (runs before fused kernel each launch) ----------------
__global__ void k_reset() {
    if (threadIdx.x < 8) g_barrier[threadIdx.x] = 0u;
}

// ---------------- grid-wide barrier (requires all NB blocks co-resident) ----------------
__device__ __forceinline__ void gridbar(int k) {
    __syncthreads();
    if (threadIdx.x == 0) {
        __threadfence();
        atomicAdd(&g_barrier[k], 1u);
        while (atomicAdd(&g_barrier[k], 0u) < (u32)NB) { __nanosleep(64); }
    }
    __syncthreads();
}

// ---------------- IOU word helper (div-free w/ exact __fdiv_rn fixup) ----------------
__device__ __forceinline__ u64 iou_word(float4 a, float aarea,
                                        const float4* cb, const float* ca) {
    u64 bits = 0ull, near_ = 0ull;
    #pragma unroll 8
    for (int jt = 0; jt < 64; jt++) {
        float4 b = cb[jt];
        float ltx = fmaxf(a.x, b.x);
        float lty = fmaxf(a.y, b.y);
        float rbx = fminf(a.z, b.z);
        float rby = fminf(a.w, b.w);
        float wx = fmaxf(rbx - ltx, 0.0f);
        float wy = fmaxf(rby - lty, 0.0f);
        float inter = wx * wy;
        float denom = ((aarea + ca[jt]) - inter) + 1e-12f;
        float m = IOU_TH * denom;
        bits  |= ((u64)(inter > m)) << jt;
        near_ |= ((u64)(fabsf(inter - m) <= 2e-6f * denom)) << jt;
    }
    if (near_) {
        u64 nb = near_;
        while (nb) {
            int jt = __ffsll((long long)nb) - 1;
            nb &= nb - 1;
            float4 b = cb[jt];
            float wx = fmaxf(fminf(a.z, b.z) - fmaxf(a.x, b.x), 0.0f);
            float wy = fmaxf(fminf(a.w, b.w) - fmaxf(a.y, b.y), 0.0f);
            float inter = wx * wy;
            float denom = ((aarea + ca[jt]) - inter) + 1e-12f;
            bool supp = __fdiv_rn(inter, denom) > IOU_TH;
            bits = (bits & ~(1ull << jt)) | (((u64)supp) << jt);
        }
    }
    return bits;
}

// ---------------- fused kernel ----------------
extern __shared__ u64 s_cache[];   // 1024 x 16 u64 = 128KB (block 0 scan cache)

__global__ void __launch_bounds__(TPB, 1)
k_fused(const float2* __restrict__ cls,
        const float4* __restrict__ loc,
        const float4* __restrict__ anc,
        float* __restrict__ out) {
    __shared__ float4 s_cb[64];
    __shared__ float  s_ca[64];
    __shared__ u64    s_rem[NWRD];
    __shared__ int    s_sel[K_POST];
    __shared__ u32    s_ls[TPB];
    __shared__ u32    s_off[TPB];

    const int tid  = threadIdx.x;
    const int flat = blockIdx.x * TPB + tid;

    // ========== Phase A: score + decode + key + histogram; zero g_valid ==========
    if (flat < NWRD) g_valid[flat] = 0ull;
    for (int n = flat; n < NN; n += TOT) {
        float2 c = cls[n];
        float m  = fmaxf(c.x, c.y);
        float e0 = expf(c.x - m);
        float e1 = expf(c.y - m);
        float s  = __fdiv_rn(e1, e0 + e1);

        float4 A = anc[n];
        float pcx = (A.z + A.x) * 0.5f;
        float pcy = (A.w + A.y) * 0.5f;
        float pw  = A.z - A.x;
        float ph  = A.w - A.y;

        float4 L = loc[n];
        float cx = L.x * pw + pcx;
        float cy = L.y * ph + pcy;
        float w  = expf(L.z) * pw;
        float h  = expf(L.w) * ph;

        float X0 = fminf(fmaxf(cx - w * 0.5f, 0.0f), 1.0f);
        float Y0 = fminf(fmaxf(cy - h * 0.5f, 0.0f), 1.0f);
        float X1 = fminf(fmaxf(cx + w * 0.5f, 0.0f), 1.0f);
        float Y1 = fminf(fmaxf(cy + h * 0.5f, 0.0f), 1.0f);

        bool valid = ((X1 - X0) >= MIN_SZ) && ((Y1 - Y0) >= MIN_SZ);
        float sm = valid ? s : -1.0f;

        u32 b  = __float_as_uint(sm);
        u32 fk = b ^ ((b >> 31) ? 0xFFFFFFFFu : 0x80000000u);

        g_keys[n]  = ((u64)fk << 32) | (u32)(~(u32)n);
        g_boxes[n] = make_float4(X0, Y0, X1, Y1);
        atomicAdd(&g_hist[fk >> 16], 1u);
    }
    gridbar(0);

    // ========== Phase B: bucket suffix sums + threshold (block 0) ==========
    if (blockIdx.x == 0) {
        u32 ssum = 0;
        #pragma unroll 8
        for (int b2 = 0; b2 < 128; b2++) ssum += g_hist[tid * 128 + b2];
        s_ls[tid] = ssum;
        __syncthreads();
        if (tid == 0) {
            u32 acc = 0;
            for (int c2 = TPB - 1; c2 >= 0; c2--) { s_off[c2] = acc; acc += s_ls[c2]; }
        }
        __syncthreads();
        u32 acc = s_off[tid];
        for (int b2 = 127; b2 >= 0; b2--) {
            int idx = tid * 128 + b2;
            u32 prev = acc;
            acc += g_hist[idx];
            g_suf[idx] = acc;
            if (prev < (u32)K_PRE && acc >= (u32)K_PRE) g_thresh = (u32)idx;
        }
    }
    gridbar(1);

    // ========== Phase C: compact candidates into per-bucket regions ==========
    {
        u32 thr = g_thresh;
        for (int n = flat; n < NN; n += TOT) {
            u64 k = g_keys[n];
            u32 b = (u32)(k >> 48);
            if (b >= thr) {
                u32 pos = g_suf[b + 1] + atomicAdd(&g_bcnt[b], 1u);
                if (pos < CAP) g_cand[pos] = k;
            }
        }
    }
    gridbar(2);

    // ========== Phase D: within-bucket rank + scatter; zero hist/bcnt ==========
    {
        u32 thr = g_thresh;
        u32 M = g_suf[thr]; if (M > CAP) M = CAP;
        u32 i = (u32)flat;
        if (i < M) {
            u64 key = __ldcg(&g_cand[i]);
            u32 b = (u32)(key >> 48);
            u32 start = g_suf[b + 1];
            u32 end   = g_suf[b]; if (end > M) end = M;
            u32 rank = start;
            for (u32 j = start; j < end; j++) rank += (__ldcg(&g_cand[j]) > key);
            if (rank < K_PRE) {
                u32 idx = ~(u32)key;
                g_sbox[rank] = g_boxes[idx];
                if ((u32)(key >> 32) >= 0x80000000u)
                    atomicOr(&g_valid[rank >> 6], 1ull << (rank & 63));
            }
        }
        for (u32 z = (u32)flat; z < 65536u; z += TOT) { g_hist[z] = 0u; g_bcnt[z] = 0u; }
    }
    gridbar(3);

    // ========== Phase E: full suppression matrix (512-row x 64-col strips) ==========
    for (int s = blockIdx.x; s < NWRD * NSTRIPR; s += NB) {
        int c = s % NWRD;         // column word
        int r = s / NWRD;         // row strip
        if (c * 64 + 63 < r * TPB) continue;   // entirely below diagonal: never read
        __syncthreads();
        if (tid < 64) {
            int j = c * 64 + tid;
            float4 bb = (j < K_PRE) ? __ldcg(&g_sbox[j]) : make_float4(0.f, 0.f, 0.f, 0.f);
            s_cb[tid] = bb;
            s_ca[tid] = (bb.z - bb.x) * (bb.w - bb.y);
        }
        __syncthreads();
        int i = r * TPB + tid;
        if (i < K_PRE) {
            float4 a = __ldcg(&g_sbox[i]);
            float aarea = (a.z - a.x) * (a.w - a.y);
            u64 bits = iou_word(a, aarea, s_cb, s_ca);
            int iw = i >> 6;
            if (c == iw) {
                int bb = i & 63;
                bits &= (bb == 63) ? 0ull : (~0ull << (bb + 1));   // j > i
            } else if (c < iw) {
                bits = 0ull;
            }
            if (c == NWRD - 1) bits &= 0x0000FFFFFFFFFFFFull;      // j < 6000
            g_supp[(size_t)i * NWRD + c] = bits;
        }
    }
    gridbar(4);

    // ========== Phase F: greedy scan (block 0) ==========
    if (blockIdx.x != 0) return;

    // load top-left CROWS x CWRD block of suppression matrix into smem
    for (int t = tid; t < CROWS * CWRD; t += TPB) {
        int rr = t >> 4, cc = t & 15;
        s_cache[t] = __ldcg(&g_supp[(size_t)rr * NWRD + cc]);
    }
    if (tid < NWRD) s_rem[tid] = 0ull;
    __syncthreads();
    if (tid >= 32) return;

    {
        const int lane = tid;
        int cnt = 0;
        bool full_mode = false;
        for (int w = 0; w < NWRD && cnt < K_POST; w++) {
            if (w >= CWRD && !full_mode) {
                // lazily reconstruct far rem words from keeps so far
                for (int k2 = 0; k2 < cnt; k2++) {
                    int i = s_sel[k2];
                    for (int w2 = CWRD + lane; w2 < NWRD; w2 += 32)
                        s_rem[w2] |= __ldcg(&g_supp[(size_t)i * NWRD + w2]);
                }
                full_mode = true;
                __syncwarp();
            }
            u64 cur = 0ull;
            if (lane == 0) cur = __ldcg(&g_valid[w]) & ~s_rem[w];

            while (true) {
                int i = -1;
                if (lane == 0 && cur) i = w * 64 + (__ffsll((long long)cur) - 1);
                i = __shfl_sync(0xFFFFFFFFu, i, 0);
                if (i < 0) break;

                u64 myrow_w;
                if (i < CROWS && !full_mode) {
                    u64 v = 0ull;
                    if (lane < CWRD) {
                        v = s_cache[i * CWRD + lane];
                        s_rem[lane] |= v;
                    }
                    myrow_w = __shfl_sync(0xFFFFFFFFu, v, w);   // w < CWRD here
                } else {
                    u64 acc = 0ull;
                    for (int w2 = w + lane; w2 < NWRD; w2 += 32) {
                        u64 v = __ldcg(&g_supp[(size_t)i * NWRD + w2]);
                        s_rem[w2] |= v;
                        if (w2 == w) acc = v;                   // lane 0 holds word w
                    }
                    myrow_w = __shfl_sync(0xFFFFFFFFu, acc, 0);
                }
                __syncwarp();

                if (lane == 0) {
                    s_sel[cnt] = i;
                    cur &= ~(1ull << (i & 63));
                    cur &= ~myrow_w;
                }
                cnt = __shfl_sync(0xFFFFFFFFu, cnt + (lane == 0 ? 1 : 0), 0);
                if (cnt >= K_POST) break;
            }
            __syncwarp();
        }
        __syncwarp();

        // output: 300 boxes, zero-padded
        float4* out4 = reinterpret_cast<float4*>(out);
        for (int k2 = lane; k2 < K_POST; k2 += 32) {
            float4 b = make_float4(0.f, 0.f, 0.f, 0.f);
            if (k2 < cnt) b = __ldcg(&g_sbox[s_sel[k2]]);
            out4[k2] = b;
        }
    }
}

// ---------------- launch ----------------
extern "C" void kernel_launch(void* const* d_in, const int* in_sizes, int n_in,
                              void* d_out, int out_size) {
    const float2* cls = (const float2*)d_in[0];   // (1, N, 2)
    const float4* loc = (const float4*)d_in[1];   // (1, N, 4)
    const float4* anc = (const float4*)d_in[2];   // (N, 4)
    float* out = (float*)d_out;                   // (300, 4)

    static int smem_set = 0;
    if (!smem_set) {
        cudaFuncSetAttribute((const void*)k_fused,
                             cudaFuncAttributeMaxDynamicSharedMemorySize,
                             CROWS * CWRD * (int)sizeof(u64));
        smem_set = 1;
    }

    k_reset<<<1, 32>>>();
    k_fused<<<NB, TPB, CROWS * CWRD * sizeof(u64)>>>(cls, loc, anc, out);
}

// round 4
// speedup vs baseline: 2.2259x; 1.4026x over previous
#include <cuda_runtime.h>
#include <cuda_bf16.h>
#include <cstdint>

#define NN      202500
#define K_PRE   6000
#define K_POST  300
#define NWRD    94
#define CAP     16384
#define NB      148
#define TPB     512
#define TOT     (NB*TPB)
#define IOU_TH  0.7f
#define MIN_SZ  0.016f
#define W1      1024            // window candidates
#define WW      16              // window words
#define NSTRIPR 12

typedef unsigned long long u64;
typedef unsigned int u32;

__device__ u64    g_keys[NN];
__device__ float4 g_boxes[NN];
__device__ u32    g_hist[65536];
__device__ u32    g_bcnt[65536];
__device__ u32    g_suf[65537];
__device__ u32    g_thresh;
__device__ u64    g_cand[CAP];
__device__ float4 g_sbox[K_PRE];
__device__ u64    g_valid[NWRD];
__device__ u64    g_wsupp[W1 * WW];
__device__ u64    g_supp[(size_t)K_PRE * NWRD];
__device__ u32    g_barrier[8];
__device__ int    g_fb;

__global__ void k_reset() { if (threadIdx.x < 8) g_barrier[threadIdx.x] = 0u; }

__device__ __forceinline__ void gridbar(int k) {
    __syncthreads();
    if (threadIdx.x == 0) {
        __threadfence();
        atomicAdd(&g_barrier[k], 1u);
        while (((volatile u32*)g_barrier)[k] < (u32)NB) __nanosleep(32);
    }
    __syncthreads();
}

extern __shared__ u64 s_dyn[];   // 128KB: D key-stage / E box-stage / F cache

__global__ void __launch_bounds__(TPB, 1)
k_fused(const float2* __restrict__ cls,
        const float4* __restrict__ loc,
        const float4* __restrict__ anc,
        float* __restrict__ out) {
    __shared__ u32    s_wt[16];
    __shared__ float4 s_cb[64];
    __shared__ float  s_ca[64];
    __shared__ int    s_sel[K_POST];
    __shared__ int    s_cnt;

    const int tid  = threadIdx.x;
    const int lane = tid & 31;
    const int wid  = tid >> 5;
    const int flat = blockIdx.x * TPB + tid;

    // ===== Phase A: score + decode + key + histogram; zero g_valid =====
    if (flat < NWRD) g_valid[flat] = 0ull;
    for (int n = flat; n < NN; n += TOT) {
        float2 c = cls[n];
        float m  = fmaxf(c.x, c.y);
        float e0 = expf(c.x - m);
        float e1 = expf(c.y - m);
        float s  = __fdiv_rn(e1, e0 + e1);

        float4 A = anc[n];
        float pcx = (A.z + A.x) * 0.5f;
        float pcy = (A.w + A.y) * 0.5f;
        float pw  = A.z - A.x;
        float ph  = A.w - A.y;

        float4 L = loc[n];
        float cx = L.x * pw + pcx;
        float cy = L.y * ph + pcy;
        float w  = expf(L.z) * pw;
        float h  = expf(L.w) * ph;

        float X0 = fminf(fmaxf(cx - w * 0.5f, 0.0f), 1.0f);
        float Y0 = fminf(fmaxf(cy - h * 0.5f, 0.0f), 1.0f);
        float X1 = fminf(fmaxf(cx + w * 0.5f, 0.0f), 1.0f);
        float Y1 = fminf(fmaxf(cy + h * 0.5f, 0.0f), 1.0f);

        bool valid = ((X1 - X0) >= MIN_SZ) && ((Y1 - Y0) >= MIN_SZ);
        float sm = valid ? s : -1.0f;

        u32 b  = __float_as_uint(sm);
        u32 fk = b ^ ((b >> 31) ? 0xFFFFFFFFu : 0x80000000u);

        g_keys[n]  = ((u64)fk << 32) | (u32)(~(u32)n);
        g_boxes[n] = make_float4(X0, Y0, X1, Y1);
        atomicAdd(&g_hist[fk >> 16], 1u);
    }
    gridbar(0);

    // ===== Phase B: suffix sums + threshold (block 0, log-depth scan) =====
    if (blockIdx.x == 0) {
        u32 ssum = 0;
        #pragma unroll 16
        for (int b = 0; b < 128; b++) ssum += g_hist[tid * 128 + b];
        u32 v = ssum;
        #pragma unroll
        for (int d = 1; d < 32; d <<= 1) {
            u32 o = __shfl_down_sync(0xFFFFFFFFu, v, d);
            if (lane < 32 - d) v += o;
        }
        if (lane == 0) s_wt[wid] = v;
        __syncthreads();
        if (tid < 16) {
            u32 t = s_wt[tid];
            #pragma unroll
            for (int d = 1; d < 16; d <<= 1) {
                u32 o = __shfl_down_sync(0x0000FFFFu, t, d);
                if (tid < 16 - d) t += o;
            }
            s_wt[tid] = t;
        }
        __syncthreads();
        u32 above = (wid < 15) ? s_wt[wid + 1] : 0u;
        u32 acc = (v + above) - ssum;     // sum over buckets above my range
        #pragma unroll 8
        for (int b = 127; b >= 0; b--) {
            int idx = tid * 128 + b;
            u32 prev = acc;
            acc += g_hist[idx];
            g_suf[idx] = acc;
            if (prev < (u32)K_PRE && acc >= (u32)K_PRE) g_thresh = (u32)idx;
        }
    }
    gridbar(1);

    // ===== Phase C: compact candidates into per-bucket regions =====
    {
        u32 thr = g_thresh;
        for (int n = flat; n < NN; n += TOT) {
            u64 k = g_keys[n];
            u32 b = (u32)(k >> 48);
            if (b >= thr) {
                u32 pos = g_suf[b + 1] + atomicAdd(&g_bcnt[b], 1u);
                if (pos < CAP) g_cand[pos] = k;
            }
        }
    }
    gridbar(2);

    // ===== Phase D: stage keys in smem; within-bucket rank; zero hist =====
    {
        u32 thr = g_thresh;
        u32 M = g_suf[thr]; if (M > CAP) M = CAP;
        for (u32 t = (u32)tid; t < M; t += TPB) s_dyn[t] = __ldcg(&g_cand[t]);
        __syncthreads();
        u32 i = (u32)flat;
        if (i < M) {
            u64 key = s_dyn[i];
            u32 b = (u32)(key >> 48);
            u32 start = g_suf[b + 1];
            u32 end   = g_suf[b]; if (end > M) end = M;
            u32 rank = start;
            #pragma unroll 8
            for (u32 j = start; j < end; j++) rank += (s_dyn[j] > key);
            if (rank < K_PRE) {
                u32 idx = ~(u32)key;
                g_sbox[rank] = g_boxes[idx];
                if ((u32)(key >> 32) >= 0x80000000u)
                    atomicOr(&g_valid[rank >> 6], 1ull << (rank & 63));
            }
        }
        for (u32 z = (u32)flat; z < 65536u; z += TOT) { g_hist[z] = 0u; g_bcnt[z] = 0u; }
    }
    gridbar(3);

    // ===== Phase E: window suppression matrix (1024 x 1024) =====
    {
        float4* sb = (float4*)s_dyn;            // 1024 boxes (16KB)
        float*  sa = (float*)(sb + W1);         // 1024 areas (4KB)
        __syncthreads();
        for (int t = tid; t < W1; t += TPB) {
            float4 b = __ldcg(&g_sbox[t]);
            sb[t] = b;
            sa[t] = (b.z - b.x) * (b.w - b.y);
        }
        __syncthreads();

        int task = flat;                        // quarter-word tasks: W1*WW*4 = 65536
        int word = task >> 2;
        int i    = word >> 4;
        int c    = word & 15;
        int sub  = task & 3;
        u64 bits = 0ull;
        bool has = (task < W1 * WW * 4);
        if (has) {
            int iw = i >> 6;
            if (c >= iw) {
                float4 a = sb[i];
                float aarea = sa[i];
                int j0 = c * 64 + sub * 16;
                u32 lb = 0, ln = 0;
                #pragma unroll 16
                for (int jt = 0; jt < 16; jt++) {
                    float4 b = sb[j0 + jt];
                    float wx = fmaxf(fminf(a.z, b.z) - fmaxf(a.x, b.x), 0.0f);
                    float wy = fmaxf(fminf(a.w, b.w) - fmaxf(a.y, b.y), 0.0f);
                    float inter = wx * wy;
                    float denom = ((aarea + sa[j0 + jt]) - inter) + 1e-12f;
                    float m = IOU_TH * denom;
                    lb |= ((u32)(inter > m)) << jt;
                    ln |= ((u32)(fabsf(inter - m) <= 2e-6f * denom)) << jt;
                }
                while (ln) {   // rare exact fixup with reference division
                    int jt = __ffs(ln) - 1; ln &= ln - 1;
                    float4 b = sb[j0 + jt];
                    float wx = fmaxf(fminf(a.z, b.z) - fmaxf(a.x, b.x), 0.0f);
                    float wy = fmaxf(fminf(a.w, b.w) - fmaxf(a.y, b.y), 0.0f);
                    float inter = wx * wy;
                    float denom = ((aarea + sa[j0 + jt]) - inter) + 1e-12f;
                    bool supp = __fdiv_rn(inter, denom) > IOU_TH;
                    lb = (lb & ~(1u << jt)) | (((u32)supp) << jt);
                }
                bits = ((u64)lb) << (16 * sub);
            }
        }
        bits |= __shfl_xor_sync(0xFFFFFFFFu, bits, 1);
        bits |= __shfl_xor_sync(0xFFFFFFFFu, bits, 2);
        if (has && sub == 0) {
            int iw = i >> 6;
            if (c == iw) {
                int bi = i & 63;
                bits &= (bi == 63) ? 0ull : (~0ull << (bi + 1));   // j > i
            }
            g_wsupp[word] = bits;
        }
    }
    gridbar(4);

    // ===== Phase F: window scan (block 0) =====
    if (blockIdx.x == 0) {
        u64* sc = s_dyn;    // 1024 x 16 cache (128KB)
        __syncthreads();
        for (int t = tid; t < W1 * WW; t += TPB) sc[t] = __ldcg(&g_wsupp[t]);
        __syncthreads();
        if (tid < 32) {
            u64 rem = 0ull;
            u64 myvalid = (lane < WW) ? __ldcg(&g_valid[lane]) : 0ull;
            int cnt = 0;
            for (int w = 0; w < WW && cnt < K_POST; w++) {
                u64 cur = __shfl_sync(0xFFFFFFFFu, myvalid & ~rem, w);
                while (cur && cnt < K_POST) {
                    int i = w * 64 + (__ffsll((long long)cur) - 1);
                    u64 row = (lane < WW) ? sc[i * WW + lane] : 0ull;
                    rem |= row;
                    u64 roww = __shfl_sync(0xFFFFFFFFu, row, w);
                    cur &= ~roww;
                    cur &= ~(1ull << (i & 63));
                    if (lane == 0) s_sel[cnt] = i;
                    cnt++;
                }
            }
            __syncwarp();
            if (lane == 0) s_cnt = cnt;
            __syncwarp();
            if (cnt >= K_POST) {   // success: write output now
                float4* out4 = reinterpret_cast<float4*>(out);
                for (int k = lane; k < K_POST; k += 32)
                    out4[k] = __ldcg(&g_sbox[s_sel[k]]);
            }
        }
        __syncthreads();
        if (tid == 0) g_fb = (s_cnt >= K_POST) ? 0 : 1;
    }
    gridbar(5);

    if (((volatile int*)&g_fb)[0] == 0) return;

    // ===== Fallback: full suppression matrix + full scan =====
    for (int s = blockIdx.x; s < NWRD * NSTRIPR; s += NB) {
        int c = s % NWRD;
        int r = s / NWRD;
        if (c * 64 + 63 < r * TPB) continue;
        __syncthreads();
        if (tid < 64) {
            int j = c * 64 + tid;
            float4 bb = (j < K_PRE) ? __ldcg(&g_sbox[j]) : make_float4(0.f, 0.f, 0.f, 0.f);
            s_cb[tid] = bb;
            s_ca[tid] = (bb.z - bb.x) * (bb.w - bb.y);
        }
        __syncthreads();
        int i = r * TPB + tid;
        if (i < K_PRE) {
            int iw = i >> 6;
            if (c >= iw) {
                float4 a = __ldcg(&g_sbox[i]);
                float aarea = (a.z - a.x) * (a.w - a.y);
                u64 bits = 0ull, near_ = 0ull;
                #pragma unroll 8
                for (int jt = 0; jt < 64; jt++) {
                    float4 b = s_cb[jt];
                    float wx = fmaxf(fminf(a.z, b.z) - fmaxf(a.x, b.x), 0.0f);
                    float wy = fmaxf(fminf(a.w, b.w) - fmaxf(a.y, b.y), 0.0f);
                    float inter = wx * wy;
                    float denom = ((aarea + s_ca[jt]) - inter) + 1e-12f;
                    float m = IOU_TH * denom;
                    bits  |= ((u64)(inter > m)) << jt;
                    near_ |= ((u64)(fabsf(inter - m) <= 2e-6f * denom)) << jt;
                }
                while (near_) {
                    int jt = __ffsll((long long)near_) - 1; near_ &= near_ - 1;
                    float4 b = s_cb[jt];
                    float wx = fmaxf(fminf(a.z, b.z) - fmaxf(a.x, b.x), 0.0f);
                    float wy = fmaxf(fminf(a.w, b.w) - fmaxf(a.y, b.y), 0.0f);
                    float inter = wx * wy;
                    float denom = ((aarea + s_ca[jt]) - inter) + 1e-12f;
                    bool supp = __fdiv_rn(inter, denom) > IOU_TH;
                    bits = (bits & ~(1ull << jt)) | (((u64)supp) << jt);
                }
                if (c == iw) {
                    int bi = i & 63;
                    bits &= (bi == 63) ? 0ull : (~0ull << (bi + 1));
                }
                if (c == NWRD - 1) bits &= 0x0000FFFFFFFFFFFFull;
                g_supp[(size_t)i * NWRD + c] = bits;
            }
        }
    }
    gridbar(6);

    if (blockIdx.x != 0) return;
    if (tid >= 32) return;
    {
        u64 rem0 = 0, rem1 = 0, rem2 = 0;
        u64 v0 = __ldcg(&g_valid[lane]);
        u64 v1 = __ldcg(&g_valid[lane + 32]);
        u64 v2 = (lane < NWRD - 64) ? __ldcg(&g_valid[lane + 64]) : 0ull;
        int cnt = 0;
        for (int w = 0; w < NWRD && cnt < K_POST; w++) {
            int hi = w >> 5, sl = w & 31;
            u64 vv = hi == 0 ? v0 : (hi == 1 ? v1 : v2);
            u64 rr = hi == 0 ? rem0 : (hi == 1 ? rem1 : rem2);
            u64 cur = __shfl_sync(0xFFFFFFFFu, vv & ~rr, sl);
            while (cur && cnt < K_POST) {
                int i = w * 64 + (__ffsll((long long)cur) - 1);
                int iw = i >> 6;
                const u64* row = &g_supp[(size_t)i * NWRD];
                u64 r0 = (lane      >= iw) ? __ldcg(&row[lane])      : 0ull;
                u64 r1 = (lane + 32 >= iw) ? __ldcg(&row[lane + 32]) : 0ull;
                u64 r2 = (lane < NWRD - 64 && lane + 64 >= iw) ? __ldcg(&row[lane + 64]) : 0ull;
                rem0 |= r0; rem1 |= r1; rem2 |= r2;
                u64 rw = hi == 0 ? r0 : (hi == 1 ? r1 : r2);
                u64 roww = __shfl_sync(0xFFFFFFFFu, rw, sl);
                cur &= ~roww;
                cur &= ~(1ull << (i & 63));
                if (lane == 0) s_sel[cnt] = i;
                cnt++;
            }
        }
        __syncwarp();
        float4* out4 = reinterpret_cast<float4*>(out);
        for (int k = lane; k < K_POST; k += 32) {
            float4 b = make_float4(0.f, 0.f, 0.f, 0.f);
            if (k < cnt) b = __ldcg(&g_sbox[s_sel[k]]);
            out4[k] = b;
        }
    }
}

extern "C" void kernel_launch(void* const* d_in, const int* in_sizes, int n_in,
                              void* d_out, int out_size) {
    const float2* cls = (const float2*)d_in[0];
    const float4* loc = (const float4*)d_in[1];
    const float4* anc = (const float4*)d_in[2];
    float* out = (float*)d_out;

    cudaFuncSetAttribute((const void*)k_fused,
                         cudaFuncAttributeMaxDynamicSharedMemorySize, 131072);

    k_reset<<<1, 32>>>();
    k_fused<<<NB, TPB, 131072>>>(cls, loc, anc, out);
}

// round 7
// speedup vs baseline: 2.2363x; 1.0047x over previous
#include <cuda_runtime.h>
#include <cuda_bf16.h>
#include <cstdint>

#define NN      202500
#define K_PRE   6000
#define K_POST  300
#define NWRD    94
#define CAP     16384
#define NB      148
#define TPB     512
#define TOT     (NB*TPB)
#define IOU_TH  0.7f
#define MIN_SZ  0.016f
#define W1      1024            // window candidates
#define WW      16              // window words
#define NSTRIPR 12
#define FCOL    (NWRD - WW)     // fallback cols 16..93 = 78

typedef unsigned long long u64;
typedef unsigned int u32;

__device__ u64    g_keys[NN];
__device__ float4 g_boxes[NN];
__device__ u32    g_hist[65536];
__device__ u32    g_bcnt[65536];
__device__ u32    g_suf[65537];
__device__ u32    g_thresh;
__device__ u64    g_cand[CAP];
__device__ float4 g_sbox[K_PRE];
__device__ u64    g_valid[NWRD];
__device__ u64    g_wsupp[W1 * WW];
__device__ u64    g_supp[(size_t)K_PRE * NWRD];
__device__ u32    g_barrier[8];
__device__ int    g_fb;
__device__ int    g_cnt;
__device__ int    g_klist[K_POST];

__global__ void k_reset() { if (threadIdx.x < 8) g_barrier[threadIdx.x] = 0u; }

__device__ __forceinline__ void gridbar(int k) {
    __syncthreads();
    if (threadIdx.x == 0) {
        __threadfence();
        atomicAdd(&g_barrier[k], 1u);
        while (((volatile u32*)g_barrier)[k] < (u32)NB) __nanosleep(32);
    }
    __syncthreads();
}

extern __shared__ u64 s_dyn[];   // 128KB

// =================== k_main: phases A-F ===================
__global__ void __launch_bounds__(TPB, 1)
k_main(const float2* __restrict__ cls,
       const float4* __restrict__ loc,
       const float4* __restrict__ anc,
       float* __restrict__ out) {
    __shared__ u32 s_wt[16];
    __shared__ int s_sel[K_POST];
    __shared__ int s_cnt;

    const int tid  = threadIdx.x;
    const int lane = tid & 31;
    const int wid  = tid >> 5;
    const int flat = blockIdx.x * TPB + tid;

    // ===== A: score + decode + key + histogram =====
    if (flat < NWRD) g_valid[flat] = 0ull;
    for (int n = flat; n < NN; n += TOT) {
        float2 c = cls[n];
        float m  = fmaxf(c.x, c.y);
        float e0 = expf(c.x - m);
        float e1 = expf(c.y - m);
        float s  = __fdiv_rn(e1, e0 + e1);

        float4 A = anc[n];
        float pcx = (A.z + A.x) * 0.5f;
        float pcy = (A.w + A.y) * 0.5f;
        float pw  = A.z - A.x;
        float ph  = A.w - A.y;

        float4 L = loc[n];
        float cx = L.x * pw + pcx;
        float cy = L.y * ph + pcy;
        float w  = expf(L.z) * pw;
        float h  = expf(L.w) * ph;

        float X0 = fminf(fmaxf(cx - w * 0.5f, 0.0f), 1.0f);
        float Y0 = fminf(fmaxf(cy - h * 0.5f, 0.0f), 1.0f);
        float X1 = fminf(fmaxf(cx + w * 0.5f, 0.0f), 1.0f);
        float Y1 = fminf(fmaxf(cy + h * 0.5f, 0.0f), 1.0f);

        bool valid = ((X1 - X0) >= MIN_SZ) && ((Y1 - Y0) >= MIN_SZ);
        float sm = valid ? s : -1.0f;

        u32 b  = __float_as_uint(sm);
        u32 fk = b ^ ((b >> 31) ? 0xFFFFFFFFu : 0x80000000u);

        g_keys[n]  = ((u64)fk << 32) | (u32)(~(u32)n);
        g_boxes[n] = make_float4(X0, Y0, X1, Y1);
        atomicAdd(&g_hist[fk >> 16], 1u);
    }
    gridbar(0);

    // ===== B: suffix sums + threshold (block 0) =====
    if (blockIdx.x == 0) {
        u32 ssum = 0;
        #pragma unroll 16
        for (int b = 0; b < 128; b++) ssum += g_hist[tid * 128 + b];
        u32 v = ssum;
        #pragma unroll
        for (int d = 1; d < 32; d <<= 1) {
            u32 o = __shfl_down_sync(0xFFFFFFFFu, v, d);
            if (lane < 32 - d) v += o;
        }
        if (lane == 0) s_wt[wid] = v;
        __syncthreads();
        if (tid < 16) {
            u32 t = s_wt[tid];
            #pragma unroll
            for (int d = 1; d < 16; d <<= 1) {
                u32 o = __shfl_down_sync(0x0000FFFFu, t, d);
                if (tid < 16 - d) t += o;
            }
            s_wt[tid] = t;
        }
        __syncthreads();
        u32 above = (wid < 15) ? s_wt[wid + 1] : 0u;
        u32 acc = (v + above) - ssum;
        #pragma unroll 8
        for (int b = 127; b >= 0; b--) {
            int idx = tid * 128 + b;
            u32 prev = acc;
            acc += g_hist[idx];
            g_suf[idx] = acc;
            if (prev < (u32)K_PRE && acc >= (u32)K_PRE) g_thresh = (u32)idx;
        }
    }
    gridbar(1);

    // ===== C: compact =====
    {
        u32 thr = g_thresh;
        for (int n = flat; n < NN; n += TOT) {
            u64 k = g_keys[n];
            u32 b = (u32)(k >> 48);
            if (b >= thr) {
                u32 pos = g_suf[b + 1] + atomicAdd(&g_bcnt[b], 1u);
                if (pos < CAP) g_cand[pos] = k;
            }
        }
    }
    gridbar(2);

    // ===== D: rank via smem-staged keys; zero hist =====
    {
        u32 thr = g_thresh;
        u32 M = g_suf[thr]; if (M > CAP) M = CAP;
        for (u32 t = (u32)tid; t < M; t += TPB) s_dyn[t] = __ldcg(&g_cand[t]);
        __syncthreads();
        u32 i = (u32)flat;
        if (i < M) {
            u64 key = s_dyn[i];
            u32 b = (u32)(key >> 48);
            u32 start = g_suf[b + 1];
            u32 end   = g_suf[b]; if (end > M) end = M;
            u32 rank = start;
            #pragma unroll 8
            for (u32 j = start; j < end; j++) rank += (s_dyn[j] > key);
            if (rank < K_PRE) {
                u32 idx = ~(u32)key;
                g_sbox[rank] = g_boxes[idx];
                if ((u32)(key >> 32) >= 0x80000000u)
                    atomicOr(&g_valid[rank >> 6], 1ull << (rank & 63));
            }
        }
        for (u32 z = (u32)flat; z < 65536u; z += TOT) { g_hist[z] = 0u; g_bcnt[z] = 0u; }
    }
    gridbar(3);

    // ===== E: window suppression matrix (1024 x 1024) =====
    {
        float4* sb = (float4*)s_dyn;
        float*  sa = (float*)(sb + W1);
        __syncthreads();
        for (int t = tid; t < W1; t += TPB) {
            float4 b = __ldcg(&g_sbox[t]);
            sb[t] = b;
            sa[t] = (b.z - b.x) * (b.w - b.y);
        }
        __syncthreads();

        int task = flat;
        int word = task >> 2;
        int i    = word >> 4;
        int c    = word & 15;
        int sub  = task & 3;
        u64 bits = 0ull;
        bool has = (task < W1 * WW * 4);
        if (has) {
            int iw = i >> 6;
            if (c >= iw) {
                float4 a = sb[i];
                float aarea = sa[i];
                int j0 = c * 64 + sub * 16;
                u32 lb = 0, ln = 0;
                #pragma unroll 16
                for (int jt = 0; jt < 16; jt++) {
                    float4 b = sb[j0 + jt];
                    float wx = fmaxf(fminf(a.z, b.z) - fmaxf(a.x, b.x), 0.0f);
                    float wy = fmaxf(fminf(a.w, b.w) - fmaxf(a.y, b.y), 0.0f);
                    float inter = wx * wy;
                    float denom = ((aarea + sa[j0 + jt]) - inter) + 1e-12f;
                    float m = IOU_TH * denom;
                    lb |= ((u32)(inter > m)) << jt;
                    ln |= ((u32)(fabsf(inter - m) <= 2e-6f * denom)) << jt;
                }
                while (ln) {
                    int jt = __ffs(ln) - 1; ln &= ln - 1;
                    float4 b = sb[j0 + jt];
                    float wx = fmaxf(fminf(a.z, b.z) - fmaxf(a.x, b.x), 0.0f);
                    float wy = fmaxf(fminf(a.w, b.w) - fmaxf(a.y, b.y), 0.0f);
                    float inter = wx * wy;
                    float denom = ((aarea + sa[j0 + jt]) - inter) + 1e-12f;
                    bool supp = __fdiv_rn(inter, denom) > IOU_TH;
                    lb = (lb & ~(1u << jt)) | (((u32)supp) << jt);
                }
                bits = ((u64)lb) << (16 * sub);
            }
        }
        bits |= __shfl_xor_sync(0xFFFFFFFFu, bits, 1);
        bits |= __shfl_xor_sync(0xFFFFFFFFu, bits, 2);
        if (has && sub == 0) {
            int iw = i >> 6;
            if (c == iw) {
                int bi = i & 63;
                bits &= (bi == 63) ? 0ull : (~0ull << (bi + 1));
            }
            g_wsupp[word] = bits;
        }
    }
    gridbar(4);

    // ===== F: window scan (block 0) =====
    if (blockIdx.x != 0) return;
    {
        u64* sc = s_dyn;
        __syncthreads();
        for (int t = tid; t < W1 * WW; t += TPB) sc[t] = __ldcg(&g_wsupp[t]);
        __syncthreads();
        if (tid < 32) {
            u64 rem = 0ull;
            u64 myvalid = (lane < WW) ? __ldcg(&g_valid[lane]) : 0ull;
            int cnt = 0;
            for (int w = 0; w < WW && cnt < K_POST; w++) {
                u64 cur = __shfl_sync(0xFFFFFFFFu, myvalid & ~rem, w);
                while (cur && cnt < K_POST) {
                    int i = w * 64 + (__ffsll((long long)cur) - 1);
                    u64 row = (lane < WW) ? sc[i * WW + lane] : 0ull;
                    rem |= row;
                    u64 roww = __shfl_sync(0xFFFFFFFFu, row, w);
                    cur &= ~roww;
                    cur &= ~(1ull << (i & 63));
                    if (lane == 0) s_sel[cnt] = i;
                    cnt++;
                }
            }
            __syncwarp();
            if (lane == 0) s_cnt = cnt;
        }
        __syncthreads();
        int cnt = s_cnt;
        // persist keep list for possible continuation
        for (int k = tid; k < cnt; k += TPB) g_klist[k] = s_sel[k];
        if (cnt >= K_POST) {
            float4* out4 = reinterpret_cast<float4*>(out);
            for (int k = tid; k < K_POST; k += TPB)
                out4[k] = __ldcg(&g_sbox[s_sel[k]]);
        }
        if (tid == 0) { g_cnt = cnt; g_fb = (cnt >= K_POST) ? 0 : 1; }
    }
}

// =================== k_fall: continuation (guarded) ===================
__global__ void __launch_bounds__(TPB, 1)
k_fall(float* __restrict__ out) {
    __shared__ float4 s_cb[64];
    __shared__ float  s_ca[64];
    __shared__ int    s_sel[K_POST];

    const int tid  = threadIdx.x;
    const int lane = tid & 31;

    if (g_fb == 0) return;

    // full suppression matrix, columns 16..93 only (rows x strips)
    for (int s = blockIdx.x; s < FCOL * NSTRIPR; s += NB) {
        int c = WW + s % FCOL;
        int r = s / FCOL;
        if (c * 64 + 63 < r * TPB) continue;
        __syncthreads();
        if (tid < 64) {
            int j = c * 64 + tid;
            float4 bb = (j < K_PRE) ? __ldcg(&g_sbox[j]) : make_float4(0.f, 0.f, 0.f, 0.f);
            s_cb[tid] = bb;
            s_ca[tid] = (bb.z - bb.x) * (bb.w - bb.y);
        }
        __syncthreads();
        int i = r * TPB + tid;
        if (i < K_PRE) {
            int iw = i >> 6;
            if (c >= iw) {
                float4 a = __ldcg(&g_sbox[i]);
                float aarea = (a.z - a.x) * (a.w - a.y);
                u64 bits = 0ull, near_ = 0ull;
                #pragma unroll 8
                for (int jt = 0; jt < 64; jt++) {
                    float4 b = s_cb[jt];
                    float wx = fmaxf(fminf(a.z, b.z) - fmaxf(a.x, b.x), 0.0f);
                    float wy = fmaxf(fminf(a.w, b.w) - fmaxf(a.y, b.y), 0.0f);
                    float inter = wx * wy;
                    float denom = ((aarea + s_ca[jt]) - inter) + 1e-12f;
                    float m = IOU_TH * denom;
                    bits  |= ((u64)(inter > m)) << jt;
                    near_ |= ((u64)(fabsf(inter - m) <= 2e-6f * denom)) << jt;
                }
                while (near_) {
                    int jt = __ffsll((long long)near_) - 1; near_ &= near_ - 1;
                    float4 b = s_cb[jt];
                    float wx = fmaxf(fminf(a.z, b.z) - fmaxf(a.x, b.x), 0.0f);
                    float wy = fmaxf(fminf(a.w, b.w) - fmaxf(a.y, b.y), 0.0f);
                    float inter = wx * wy;
                    float denom = ((aarea + s_ca[jt]) - inter) + 1e-12f;
                    bool supp = __fdiv_rn(inter, denom) > IOU_TH;
                    bits = (bits & ~(1ull << jt)) | (((u64)supp) << jt);
                }
                if (c == iw) {
                    int bi = i & 63;
                    bits &= (bi == 63) ? 0ull : (~0ull << (bi + 1));
                }
                if (c == NWRD - 1) bits &= 0x0000FFFFFFFFFFFFull;
                g_supp[(size_t)i * NWRD + c] = bits;
            }
        }
    }
    gridbar(6);

    if (blockIdx.x != 0) return;

    int cnt0 = g_cnt;
    if (tid >= 32) return;
    for (int k = lane; k < cnt0; k += 32) s_sel[k] = g_klist[k];
    __syncwarp();

    // seed rem[16..93] from window keeps (parallel, high-MLP loads)
    u64 rem0 = 0, rem1 = 0, rem2 = 0;
    for (int k = 0; k < cnt0; k++) {
        const u64* row = &g_supp[(size_t)s_sel[k] * NWRD];
        rem0 |= __ldcg(&row[16 + lane]);
        rem1 |= __ldcg(&row[48 + lane]);
        if (lane < NWRD - 80) rem2 |= __ldcg(&row[80 + lane]);
    }
    u64 v0 = __ldcg(&g_valid[16 + lane]);
    u64 v1 = __ldcg(&g_valid[48 + lane]);
    u64 v2 = (lane < NWRD - 80) ? __ldcg(&g_valid[80 + lane]) : 0ull;

    int cnt = cnt0;
    for (int w = WW; w < NWRD && cnt < K_POST; w++) {
        int hi = (w - 16) >> 5, sl = (w - 16) & 31;
        u64 vv = hi == 0 ? v0 : (hi == 1 ? v1 : v2);
        u64 rr = hi == 0 ? rem0 : (hi == 1 ? rem1 : rem2);
        u64 cur = __shfl_sync(0xFFFFFFFFu, vv & ~rr, sl);
        while (cur && cnt < K_POST) {
            int i = w * 64 + (__ffsll((long long)cur) - 1);
            int iw = i >> 6;
            const u64* row = &g_supp[(size_t)i * NWRD];
            u64 r0 = (16 + lane >= iw) ? __ldcg(&row[16 + lane]) : 0ull;
            u64 r1 = (48 + lane >= iw) ? __ldcg(&row[48 + lane]) : 0ull;
            u64 r2 = (lane < NWRD - 80 && 80 + lane >= iw) ? __ldcg(&row[80 + lane]) : 0ull;
            rem0 |= r0; rem1 |= r1; rem2 |= r2;
            u64 rw = hi == 0 ? r0 : (hi == 1 ? r1 : r2);
            u64 roww = __shfl_sync(0xFFFFFFFFu, rw, sl);
            cur &= ~roww;
            cur &= ~(1ull << (i & 63));
            if (lane == 0) s_sel[cnt] = i;
            cnt++;
        }
    }
    __syncwarp();
    float4* out4 = reinterpret_cast<float4*>(out);
    for (int k = lane; k < K_POST; k += 32) {
        float4 b = make_float4(0.f, 0.f, 0.f, 0.f);
        if (k < cnt) b = __ldcg(&g_sbox[s_sel[k]]);
        out4[k] = b;
    }
}

extern "C" void kernel_launch(void* const* d_in, const int* in_sizes, int n_in,
                              void* d_out, int out_size) {
    const float2* cls = (const float2*)d_in[0];
    const float4* loc = (const float4*)d_in[1];
    const float4* anc = (const float4*)d_in[2];
    float* out = (float*)d_out;

    cudaFuncSetAttribute((const void*)k_main,
                         cudaFuncAttributeMaxDynamicSharedMemorySize, 131072);

    k_reset<<<1, 32>>>();
    k_main<<<NB, TPB, 131072>>>(cls, loc, anc, out);
    k_fall<<<NB, TPB>>>(out);
}